// round 7
// baseline (speedup 1.0000x reference)
#include <cuda_runtime.h>
#include <cuda_fp16.h>
#include <math.h>

#define MAX_NODES 50000
#define MAX_RELS  16
#define D 32

// Scratch (device globals; no allocation allowed)
__device__ __align__(16) __half g_Ph[MAX_NODES * D * 4]; // [n][o][b] halves
__device__ __align__(16) __half g_uh[MAX_NODES * D];     // init_fea @ A_w[0:32]
__device__ __align__(16) __half g_vh[MAX_NODES * D];     // init_fea @ A_w[32:64]
__device__ __align__(16) float  g_agg[MAX_NODES * D];    // curr + scatter of a*msg
__device__ __align__(16) float  g_t[MAX_RELS * D];       // attn_emb @ A_w[64:96] + A_b

struct alignas(8) H4 { __half2 a, b; };

// ---------------------------------------------------------------------------
// K1: node stage. 4 nodes/warp, persistent. No shuffles: node features are
// staged in warp-private smem and re-read as LDS.128 broadcasts; weight
// tables are stored transposed ([out][k], stride 36) so each lane's weight
// column is read as LDS.128. Block 0 also builds g_t.
// ---------------------------------------------------------------------------
__global__ void __launch_bounds__(256) k_node(
    const float* __restrict__ feat, const float* __restrict__ embed,
    const int* __restrict__ idx, const float* __restrict__ transform,
    const float* __restrict__ weight, const float* __restrict__ A_w,
    const float* __restrict__ selfw, const float* __restrict__ attn_emb,
    const float* __restrict__ A_b, float* __restrict__ out, int n_nodes) {
    // transposed weights: [table][out_col(lane)][k], stride 36 keeps float4
    // alignment (36*4B = 144B, multiple of 16)
    __shared__ __align__(16) float wT[2][32][36];  // transform halves
    __shared__ __align__(16) float wW[4][32][36];  // basis weights
    __shared__ __align__(16) float wA[2][32][36];  // A_w rows 0..63
    __shared__ __align__(16) float wS[32][36];     // self loop
    __shared__ __align__(16) float sfg[8][2][4][32]; // [warp][f/g][node j][k]

    int tid = threadIdx.x;

    // folded k_rel_t: t[r][o] = A_b[o] + sum_k attn_emb[r,k] * A_w[64+k, o]
    if (blockIdx.x == 0) {
        int r0 = tid >> 5;        // 0..7
        int o = tid & 31;
#pragma unroll
        for (int rr = 0; rr < 2; rr++) {
            int r = r0 + rr * 8;
            float acc = A_b[o];
#pragma unroll
            for (int k = 0; k < 32; k++)
                acc += attn_emb[r * 32 + k] * A_w[(64 + k) * 32 + o];
            g_t[r * 32 + o] = acc;
        }
    }

    // load + transpose weight tables (gmem [k][o] -> smem [o][k])
    for (int i = tid; i < 64 * 32; i += 256) {
        int k = i >> 5, o = i & 31;
        wT[k >> 5][o][k & 31] = transform[i];
    }
    for (int i = tid; i < 4 * 32 * 32; i += 256) {
        int b = i >> 10, k = (i >> 5) & 31, o = i & 31;
        wW[b][o][k] = weight[i];
    }
    for (int i = tid; i < 64 * 32; i += 256) {
        int k = i >> 5, o = i & 31;
        wA[k >> 5][o][k & 31] = A_w[i];
    }
    for (int i = tid; i < 32 * 32; i += 256) {
        int k = i >> 5, o = i & 31;
        wS[o][k] = selfw[i];
    }
    __syncthreads();

    int lane = tid & 31;
    int w = tid >> 5;                                  // warp in block
    int warps_per_grid = gridDim.x * 8;
    int warp0 = blockIdx.x * 8 + w;
    int n_tasks = (n_nodes + 3) >> 2;                  // warp-tasks of 4 nodes

    for (int task = warp0; task < n_tasks; task += warps_per_grid) {
        int n0 = task * 4;

        bool val[4];
#pragma unroll
        for (int j = 0; j < 4; j++) {
            int n = n0 + j;
            val[j] = (n < n_nodes);
            float fj = 0.f, gj = 0.f;
            if (val[j]) {
                fj = feat[n * 32 + lane];
                gj = embed[(long)idx[n] * 32 + lane];
            }
            sfg[w][0][j][lane] = fj;   // lane index == k index
            sfg[w][1][j][lane] = gj;
        }
        __syncwarp();

        // Phase A: init_fea (lane = output column)
        float fea[4] = {0.f, 0.f, 0.f, 0.f};
#pragma unroll
        for (int kg = 0; kg < 8; kg++) {
            float4 t1 = *reinterpret_cast<const float4*>(&wT[0][lane][kg * 4]);
            float4 t2 = *reinterpret_cast<const float4*>(&wT[1][lane][kg * 4]);
#pragma unroll
            for (int j = 0; j < 4; j++) {
                float4 a = *reinterpret_cast<const float4*>(&sfg[w][0][j][kg * 4]);
                float4 b = *reinterpret_cast<const float4*>(&sfg[w][1][j][kg * 4]);
                fea[j] += a.x * t1.x + a.y * t1.y + a.z * t1.z + a.w * t1.w
                        + b.x * t2.x + b.y * t2.y + b.z * t2.z + b.w * t2.w;
            }
        }
        __syncwarp();   // done reading sfg before overwrite

        // stage fea for phase B broadcasts
#pragma unroll
        for (int j = 0; j < 4; j++) sfg[w][0][j][lane] = fea[j];
        __syncwarp();

        // Phase B: 7 downstream projections of init_fea
        float P0[4] = {0,0,0,0}, P1[4] = {0,0,0,0};
        float P2[4] = {0,0,0,0}, P3[4] = {0,0,0,0};
        float u[4] = {0,0,0,0}, v[4] = {0,0,0,0}, c[4] = {0,0,0,0};
#pragma unroll
        for (int kg = 0; kg < 8; kg++) {
            float4 w0 = *reinterpret_cast<const float4*>(&wW[0][lane][kg * 4]);
            float4 w1 = *reinterpret_cast<const float4*>(&wW[1][lane][kg * 4]);
            float4 w2 = *reinterpret_cast<const float4*>(&wW[2][lane][kg * 4]);
            float4 w3 = *reinterpret_cast<const float4*>(&wW[3][lane][kg * 4]);
            float4 au = *reinterpret_cast<const float4*>(&wA[0][lane][kg * 4]);
            float4 av = *reinterpret_cast<const float4*>(&wA[1][lane][kg * 4]);
            float4 ac = *reinterpret_cast<const float4*>(&wS[lane][kg * 4]);
#pragma unroll
            for (int j = 0; j < 4; j++) {
                float4 s = *reinterpret_cast<const float4*>(&sfg[w][0][j][kg * 4]);
                P0[j] += s.x * w0.x + s.y * w0.y + s.z * w0.z + s.w * w0.w;
                P1[j] += s.x * w1.x + s.y * w1.y + s.z * w1.z + s.w * w1.w;
                P2[j] += s.x * w2.x + s.y * w2.y + s.z * w2.z + s.w * w2.w;
                P3[j] += s.x * w3.x + s.y * w3.y + s.z * w3.z + s.w * w3.w;
                u[j]  += s.x * au.x + s.y * au.y + s.z * au.z + s.w * au.w;
                v[j]  += s.x * av.x + s.y * av.y + s.z * av.z + s.w * av.w;
                c[j]  += s.x * ac.x + s.y * ac.y + s.z * ac.z + s.w * ac.w;
            }
        }

#pragma unroll
        for (int j = 0; j < 4; j++) {
            if (!val[j]) continue;
            int n = n0 + j;
            out[(long)n * 64 + lane] = fea[j];             // out[:,0,:]
            H4 h4;
            h4.a = __halves2half2(__float2half_rn(P0[j]), __float2half_rn(P1[j]));
            h4.b = __halves2half2(__float2half_rn(P2[j]), __float2half_rn(P3[j]));
            *reinterpret_cast<H4*>(&g_Ph[(size_t)n * 128 + lane * 4]) = h4;
            g_uh[n * 32 + lane] = __float2half_rn(u[j]);
            g_vh[n * 32 + lane] = __float2half_rn(v[j]);
            g_agg[n * 32 + lane] = c[j];
        }
        __syncwarp();   // next task's staging must not race phase-B reads
    }
}

// ---------------------------------------------------------------------------
// K2: edge stage. 8 edges per warp (two quads, unrolled x2 for MLP);
// 8 lanes per edge; each lane covers 4 output columns.
// ---------------------------------------------------------------------------
__global__ void __launch_bounds__(256) k_edge(
    const int* __restrict__ esrc, const int* __restrict__ edst,
    const int* __restrict__ etype, const float* __restrict__ w_comp,
    const float* __restrict__ B_w, const float* __restrict__ B_b, int n_edges) {
    __shared__ __align__(16) float4 s_wc[MAX_RELS];      // w_comp per rel
    __shared__ __align__(16) float4 s_t4[MAX_RELS * 8];  // attn bias per rel
    __shared__ __align__(16) float4 s_bw4[8];
    __shared__ float s_bb;

    int tid = threadIdx.x;
    if (tid < MAX_RELS)
        s_wc[tid] = reinterpret_cast<const float4*>(w_comp)[tid];
    if (tid < MAX_RELS * 8)
        s_t4[tid] = reinterpret_cast<const float4*>(g_t)[tid];
    if (tid < 8)
        s_bw4[tid] = reinterpret_cast<const float4*>(B_w)[tid];
    if (tid == 0) s_bb = B_b[0];
    __syncthreads();

    int warp = (blockIdx.x * blockDim.x + tid) >> 5;
    int lane = tid & 31;
    int sub = lane >> 3;   // quad slot (0..3)
    int g = lane & 7;      // lane within 8-lane edge group; outputs 4g..4g+3
    float4 bw = s_bw4[g];

    int e[2];
    e[0] = warp * 8 + sub;
    e[1] = e[0] + 4;

    int src[2], dst[2], ty[2];
    bool ok[2];
#pragma unroll
    for (int q = 0; q < 2; q++) {
        ok[q] = (e[q] < n_edges);
        int ee = ok[q] ? e[q] : 0;
        src[q] = esrc[ee];
        dst[q] = edst[ee];
        ty[q] = etype[ee];
    }
    if (!ok[0]) return;

    // Issue all gathers for both edges before consuming (deep MLP)
    uint4 r0[2], r1[2];
    uint2 uu[2], vv[2];
#pragma unroll
    for (int q = 0; q < 2; q++) {
        const uint4* Pp =
            reinterpret_cast<const uint4*>(g_Ph + (size_t)src[q] * 128 + g * 16);
        r0[q] = Pp[0];
        r1[q] = Pp[1];
        uu[q] = *reinterpret_cast<const uint2*>(g_uh + (size_t)src[q] * 32 + g * 4);
        vv[q] = *reinterpret_cast<const uint2*>(g_vh + (size_t)dst[q] * 32 + g * 4);
    }

#pragma unroll
    for (int q = 0; q < 2; q++) {
        if (!ok[q]) break;
        float4 cc = s_wc[ty[q]];
        float4 t4 = s_t4[ty[q] * 8 + g];

        float2 p00 = __half22float2(*reinterpret_cast<__half2*>(&r0[q].x));
        float2 p01 = __half22float2(*reinterpret_cast<__half2*>(&r0[q].y));
        float2 p10 = __half22float2(*reinterpret_cast<__half2*>(&r0[q].z));
        float2 p11 = __half22float2(*reinterpret_cast<__half2*>(&r0[q].w));
        float2 p20 = __half22float2(*reinterpret_cast<__half2*>(&r1[q].x));
        float2 p21 = __half22float2(*reinterpret_cast<__half2*>(&r1[q].y));
        float2 p30 = __half22float2(*reinterpret_cast<__half2*>(&r1[q].z));
        float2 p31 = __half22float2(*reinterpret_cast<__half2*>(&r1[q].w));

        float4 msg;
        msg.x = p00.x * cc.x + p00.y * cc.y + p01.x * cc.z + p01.y * cc.w;
        msg.y = p10.x * cc.x + p10.y * cc.y + p11.x * cc.z + p11.y * cc.w;
        msg.z = p20.x * cc.x + p20.y * cc.y + p21.x * cc.z + p21.y * cc.w;
        msg.w = p30.x * cc.x + p30.y * cc.y + p31.x * cc.z + p31.y * cc.w;

        float2 u0 = __half22float2(*reinterpret_cast<__half2*>(&uu[q].x));
        float2 u1 = __half22float2(*reinterpret_cast<__half2*>(&uu[q].y));
        float2 v0 = __half22float2(*reinterpret_cast<__half2*>(&vv[q].x));
        float2 v1 = __half22float2(*reinterpret_cast<__half2*>(&vv[q].y));

        float zx = fmaxf(u0.x + v0.x + t4.x, 0.f);
        float zy = fmaxf(u0.y + v0.y + t4.y, 0.f);
        float zz = fmaxf(u1.x + v1.x + t4.z, 0.f);
        float zw = fmaxf(u1.y + v1.y + t4.w, 0.f);

        float s = zx * bw.x + zy * bw.y + zz * bw.z + zw * bw.w;
        s += __shfl_xor_sync(0xffffffffu, s, 4);
        s += __shfl_xor_sync(0xffffffffu, s, 2);
        s += __shfl_xor_sync(0xffffffffu, s, 1);
        float a = 1.f / (1.f + __expf(-(s + s_bb)));

        float4 r = make_float4(a * msg.x, a * msg.y, a * msg.z, a * msg.w);
        atomicAdd(reinterpret_cast<float4*>(g_agg) + (size_t)dst[q] * 8 + g, r);
    }
}

// ---------------------------------------------------------------------------
// K3: h = relu(agg) -> out[:,1,:]  (float4 vectorized)
// ---------------------------------------------------------------------------
__global__ void k_final(float* __restrict__ out, int n4) {
    int i = blockIdx.x * blockDim.x + threadIdx.x;   // over n_nodes*8 float4s
    if (i >= n4) return;
    int n = i >> 3;
    int q = i & 7;
    float4 v = reinterpret_cast<const float4*>(g_agg)[i];
    float4 r = make_float4(fmaxf(v.x, 0.f), fmaxf(v.y, 0.f),
                           fmaxf(v.z, 0.f), fmaxf(v.w, 0.f));
    reinterpret_cast<float4*>(out)[(size_t)n * 16 + 8 + q] = r;
}

extern "C" void kernel_launch(void* const* d_in, const int* in_sizes, int n_in,
                              void* d_out, int out_size) {
    const float* feat      = (const float*)d_in[0];
    const float* embed     = (const float*)d_in[1];
    const float* transform = (const float*)d_in[2];
    const float* weight    = (const float*)d_in[3];
    const float* w_comp    = (const float*)d_in[4];
    const float* selfw     = (const float*)d_in[5];
    const float* A_w       = (const float*)d_in[6];
    const float* A_b       = (const float*)d_in[7];
    const float* B_w       = (const float*)d_in[8];
    const float* B_b       = (const float*)d_in[9];
    const float* attn_emb  = (const float*)d_in[10];
    const int*   idx       = (const int*)d_in[11];
    const int*   esrc      = (const int*)d_in[12];
    const int*   edst      = (const int*)d_in[13];
    const int*   ety       = (const int*)d_in[14];
    float* out = (float*)d_out;

    int n_nodes = in_sizes[0] / 32;
    int n_edges = in_sizes[12];

    int blocks1 = 592;   // persistent; ~4 blocks/SM target
    k_node<<<blocks1, 256>>>(feat, embed, idx, transform, weight, A_w, selfw,
                             attn_emb, A_b, out, n_nodes);

    int blocks2 = (n_edges + 63) / 64;  // 8 warps/block, 8 edges/warp
    k_edge<<<blocks2, 256>>>(esrc, edst, ety, w_comp, B_w, B_b, n_edges);

    int n4 = n_nodes * 8;
    int blocks3 = (n4 + 255) / 256;
    k_final<<<blocks3, 256>>>(out, n4);
}